// round 3
// baseline (speedup 1.0000x reference)
#include <cuda_runtime.h>
#include <cuda_bf16.h>

// ---------------------------------------------------------------------------
// PopulationGNN: 4-layer GCN, N=50000, IN_DIM=2000, HID=64, E=1.6M
// CSR-by-destination build once per launch, then per layer:
// GEMM -> warp-per-node register gather (self-loop fused) ->
// BN stats (2-stage deterministic) -> BN finalize -> norm/relu/res/emb fused.
// All scratch in __device__ globals referenced directly by kernels.
// ---------------------------------------------------------------------------

#define HID 64
#define MAXN 50048
#define MAXE 1600256
#define STATS_BLOCKS 256
#define SBS 256          // scan block size
#define MAXSB 256        // max scan blocks (ceil(50000/256)=196)

__device__ __align__(16) float g_XW[MAXN * HID];
__device__ __align__(16) float g_AGG[MAXN * HID];
__device__ __align__(16) float g_OUT0[MAXN * HID];
__device__ __align__(16) float g_OUT1[MAXN * HID];
__device__ int   g_DEGI[MAXN];
__device__ float g_DINV[MAXN];
__device__ int   g_ESRC[MAXE];     // CSR: source node per sorted edge
__device__ float g_EW[MAXE];       // CSR: normalized edge weight
__device__ int   g_ROWPTR[MAXN + 1];
__device__ int   g_CUR[MAXN];
__device__ int   g_ROWEXC[MAXN];
__device__ int   g_BTOT[MAXSB];
__device__ int   g_BOFF[MAXSB];
__device__ int   g_IS32;           // 1 if edges buffer is int32, 0 if int64
__device__ __align__(16) float g_PART[STATS_BLOCKS * 128];
__device__ __align__(16) float g_SS[132];  // [0:64) scale, [64:128) shift, [128] softmax w

// ---------------------------------------------------------------------------
// Edge dtype probe + CSR build.  E = logical edge count (in_sizes[1]/2).
// int32 layout: words[0..E) = src, words[E..2E) = dst.
// int64 layout: src_e = words[2e], dst_e = words[2E + 2e] (hi words all 0).
// Probe: odd words of the first E words are all zero iff int64.
// ---------------------------------------------------------------------------

__global__ void init_kernel(int n) {
    int i = blockIdx.x * blockDim.x + threadIdx.x;
    if (i < n) g_DEGI[i] = 0;
    if (i == 0) g_IS32 = 0;
}

__global__ void detect_kernel(const int* __restrict__ words, int E) {
    int i = blockIdx.x * blockDim.x + threadIdx.x;
    int idx = 2 * i + 1;            // odd words within first E words
    if (idx < E && words[idx] != 0)
        atomicOr(&g_IS32, 1);
}

__device__ __forceinline__ void decode_edge(const int* __restrict__ words, int E, int e,
                                            int& s, int& d) {
    if (g_IS32) {
        s = words[e];
        d = words[E + e];
    } else {
        s = words[2 * e];
        d = words[2 * E + 2 * e];
    }
}

__global__ void count_kernel(const int* __restrict__ words, int E) {
    int e = blockIdx.x * blockDim.x + threadIdx.x;
    if (e < E) {
        int s, d;
        decode_edge(words, E, e, s, d);
        atomicAdd(&g_DEGI[d], 1);
    }
}

__global__ void dinv_kernel(int n) {
    int i = blockIdx.x * blockDim.x + threadIdx.x;
    if (i < n) g_DINV[i] = rsqrtf((float)g_DEGI[i] + 1.0f);
}

// Hillis-Steele per-block scan; rowexc = exclusive within block, btot = block sum
__global__ void scan1_kernel(int n) {
    __shared__ int sm[SBS];
    int t = threadIdx.x;
    int i = blockIdx.x * SBS + t;
    int v = (i < n) ? g_DEGI[i] : 0;
    sm[t] = v;
    __syncthreads();
#pragma unroll
    for (int off = 1; off < SBS; off <<= 1) {
        int y = (t >= off) ? sm[t - off] : 0;
        __syncthreads();
        sm[t] += y;
        __syncthreads();
    }
    if (i < n) g_ROWEXC[i] = sm[t] - v;
    if (t == SBS - 1) g_BTOT[blockIdx.x] = sm[t];
}

__global__ void scan2_kernel(int nb) {
    __shared__ int sm[SBS];
    int t = threadIdx.x;
    int v = (t < nb) ? g_BTOT[t] : 0;
    sm[t] = v;
    __syncthreads();
#pragma unroll
    for (int off = 1; off < SBS; off <<= 1) {
        int y = (t >= off) ? sm[t - off] : 0;
        __syncthreads();
        sm[t] += y;
        __syncthreads();
    }
    if (t < nb) g_BOFF[t] = sm[t] - v;
}

__global__ void scan3_kernel(int n, int E) {
    int i = blockIdx.x * blockDim.x + threadIdx.x;
    if (i < n) {
        int r = g_ROWEXC[i] + g_BOFF[i / SBS];
        g_ROWPTR[i] = r;
        g_CUR[i] = r;
    }
    if (i == 0) g_ROWPTR[n] = E;
}

__global__ void fill_kernel(const int* __restrict__ words, int E) {
    int e = blockIdx.x * blockDim.x + threadIdx.x;
    if (e < E) {
        int s, d;
        decode_edge(words, E, e, s, d);
        int pos = atomicAdd(&g_CUR[d], 1);
        g_ESRC[pos] = s;
        g_EW[pos] = g_DINV[s] * g_DINV[d];
    }
}

// ---------------------------------------------------------------------------
// GEMM: A[M,K] @ W[K,64] -> g_XW[M,64]. BM=128, BN=64, BK=16, 256 threads,
// 8x4 microtile. K multiple of 16 (2000 or 64). A selected by src_sel:
// 0 = external (features), 1 = g_OUT0, 2 = g_OUT1.
// ---------------------------------------------------------------------------

__global__ void gemm64_kernel(const float* __restrict__ feat, int src_sel,
                              const float* __restrict__ W, int M, int K) {
    __shared__ float As[16][128];                 // [k][m]
    __shared__ __align__(16) float Bs[16][64];    // [k][n]

    const float* A = (src_sel == 0) ? feat : (src_sel == 1 ? g_OUT0 : g_OUT1);

    int t = threadIdx.x;
    int m0 = blockIdx.x * 128;

    int tr = (t >> 4) * 8;      // output row base 0..120
    int tc = (t & 15) * 4;      // output col base 0..60

    float acc[8][4];
#pragma unroll
    for (int i = 0; i < 8; i++)
#pragma unroll
        for (int j = 0; j < 4; j++) acc[i][j] = 0.0f;

    for (int k0 = 0; k0 < K; k0 += 16) {
        float4 av[2];
        int arv[2], acv[2];
#pragma unroll
        for (int i = 0; i < 2; i++) {
            int v = t + i * 256;
            arv[i] = v >> 2;              // 0..127
            acv[i] = (v & 3) * 4;         // 0,4,8,12
            int row = m0 + arv[i];
            av[i] = make_float4(0.f, 0.f, 0.f, 0.f);
            if (row < M)
                av[i] = *reinterpret_cast<const float4*>(&A[(size_t)row * K + k0 + acv[i]]);
        }
        int br = t >> 4;                  // 0..15
        int bc = (t & 15) * 4;            // 0..60
        float4 bv = *reinterpret_cast<const float4*>(&W[(size_t)(k0 + br) * HID + bc]);

        __syncthreads();
#pragma unroll
        for (int i = 0; i < 2; i++) {
            As[acv[i] + 0][arv[i]] = av[i].x;
            As[acv[i] + 1][arv[i]] = av[i].y;
            As[acv[i] + 2][arv[i]] = av[i].z;
            As[acv[i] + 3][arv[i]] = av[i].w;
        }
        *reinterpret_cast<float4*>(&Bs[br][bc]) = bv;
        __syncthreads();

#pragma unroll
        for (int k = 0; k < 16; ++k) {
            float4 aL = *reinterpret_cast<const float4*>(&As[k][tr]);
            float4 aH = *reinterpret_cast<const float4*>(&As[k][tr + 4]);
            float4 b  = *reinterpret_cast<const float4*>(&Bs[k][tc]);
            float ar8[8] = {aL.x, aL.y, aL.z, aL.w, aH.x, aH.y, aH.z, aH.w};
#pragma unroll
            for (int i = 0; i < 8; i++) {
                acc[i][0] = fmaf(ar8[i], b.x, acc[i][0]);
                acc[i][1] = fmaf(ar8[i], b.y, acc[i][1]);
                acc[i][2] = fmaf(ar8[i], b.z, acc[i][2]);
                acc[i][3] = fmaf(ar8[i], b.w, acc[i][3]);
            }
        }
    }

#pragma unroll
    for (int i = 0; i < 8; i++) {
        int row = m0 + tr + i;
        if (row < M) {
            float4 v = make_float4(acc[i][0], acc[i][1], acc[i][2], acc[i][3]);
            *reinterpret_cast<float4*>(&g_XW[(size_t)row * HID + tc]) = v;
        }
    }
}

// ---------------------------------------------------------------------------
// Gather: warp per node. AGG[v] = snorm*XW[v] + sum_{e in CSR[v]} w_e*XW[src_e]
// Each lane owns channels {lane, lane+32}.
// ---------------------------------------------------------------------------

__global__ void gather_kernel(int N) {
    int gid = blockIdx.x * blockDim.x + threadIdx.x;
    int v = gid >> 5;
    int lane = gid & 31;
    if (v >= N) return;

    int beg = g_ROWPTR[v];
    int end = g_ROWPTR[v + 1];
    float dn = g_DINV[v];
    float sn = dn * dn;
    float a0 = g_XW[v * HID + lane] * sn;
    float a1 = g_XW[v * HID + 32 + lane] * sn;

    int j = beg;
    for (; j + 1 < end; j += 2) {
        int s0 = g_ESRC[j];
        int s1 = g_ESRC[j + 1];
        float w0 = g_EW[j];
        float w1 = g_EW[j + 1];
        float x00 = g_XW[s0 * HID + lane];
        float x01 = g_XW[s0 * HID + 32 + lane];
        float x10 = g_XW[s1 * HID + lane];
        float x11 = g_XW[s1 * HID + 32 + lane];
        a0 = fmaf(w0, x00, a0);
        a1 = fmaf(w0, x01, a1);
        a0 = fmaf(w1, x10, a0);
        a1 = fmaf(w1, x11, a1);
    }
    if (j < end) {
        int s0 = g_ESRC[j];
        float w0 = g_EW[j];
        a0 = fmaf(w0, g_XW[s0 * HID + lane], a0);
        a1 = fmaf(w0, g_XW[s0 * HID + 32 + lane], a1);
    }

    g_AGG[v * HID + lane] = a0;
    g_AGG[v * HID + 32 + lane] = a1;
}

// ---------------------------------------------------------------------------
// BN stats: per-block partial sums/sumsqs per channel. Channel quad fixed per
// thread (stride = grid*block = 65536, multiple of 16).
// ---------------------------------------------------------------------------

__global__ void bn_stats_kernel(int N) {
    __shared__ float4 ssum[256];
    __shared__ float4 ssq[256];
    const float4* AGG4 = reinterpret_cast<const float4*>(g_AGG);
    int t = threadIdx.x;
    int stride = gridDim.x * blockDim.x;
    int total = N * 16;
    float4 s = make_float4(0.f, 0.f, 0.f, 0.f);
    float4 q = make_float4(0.f, 0.f, 0.f, 0.f);
    for (int i = blockIdx.x * blockDim.x + t; i < total; i += stride) {
        float4 v = AGG4[i];
        s.x += v.x; s.y += v.y; s.z += v.z; s.w += v.w;
        q.x += v.x * v.x; q.y += v.y * v.y; q.z += v.z * v.z; q.w += v.w * v.w;
    }
    ssum[t] = s;
    ssq[t] = q;
    __syncthreads();
    for (int off = 128; off >= 16; off >>= 1) {
        if (t < off) {
            float4 a = ssum[t], b = ssum[t + off];
            ssum[t] = make_float4(a.x + b.x, a.y + b.y, a.z + b.z, a.w + b.w);
            float4 c = ssq[t], d = ssq[t + off];
            ssq[t] = make_float4(c.x + d.x, c.y + d.y, c.z + d.z, c.w + d.w);
        }
        __syncthreads();
    }
    if (t < 16) {
        *reinterpret_cast<float4*>(&g_PART[blockIdx.x * 128 + t * 4]) = ssum[t];
        *reinterpret_cast<float4*>(&g_PART[blockIdx.x * 128 + 64 + t * 4]) = ssq[t];
    }
}

__global__ void bn_finalize_kernel(const float* __restrict__ gamma,
                                   const float* __restrict__ beta,
                                   const float* __restrict__ lw,
                                   int layer, int L, int N) {
    __shared__ float s_s[256];
    __shared__ float s_q[256];
    int t = threadIdx.x;
    int c = t & 63;
    int g0 = t >> 6;   // 0..3
    float s = 0.f, q = 0.f;
    for (int g = g0; g < STATS_BLOCKS; g += 4) {
        s += g_PART[g * 128 + c];
        q += g_PART[g * 128 + 64 + c];
    }
    s_s[t] = s;
    s_q[t] = q;
    __syncthreads();
    if (t < 128) { s_s[t] += s_s[t + 128]; s_q[t] += s_q[t + 128]; }
    __syncthreads();
    if (t < 64) {
        float S = s_s[t] + s_s[t + 64];
        float Q = s_q[t] + s_q[t + 64];
        float invN = 1.0f / (float)N;
        float mean = S * invN;
        float var = Q * invN - mean * mean;
        float inv = rsqrtf(var + 1e-5f);
        float sc = gamma[layer * HID + c] * inv;
        g_SS[c] = sc;
        g_SS[64 + c] = beta[layer * HID + c] - mean * sc;
    }
    if (t == 0) {
        float se = 0.f;
        for (int j = 0; j < L; j++) se += expf(lw[j]);
        g_SS[128] = expf(lw[layer]) / se;
    }
}

// ---------------------------------------------------------------------------
// Normalize + ReLU + residual + softmax-weighted emb accumulation.
// cur/prev selected from layer parity in-kernel.
// ---------------------------------------------------------------------------

__global__ void bn_norm_kernel(float4* __restrict__ EMB4, int N, int layer) {
    const float4* AGG4  = reinterpret_cast<const float4*>(g_AGG);
    const float4* PREV4 = reinterpret_cast<const float4*>((layer & 1) ? g_OUT0 : g_OUT1);
    float4* OUT4        = reinterpret_cast<float4*>((layer & 1) ? g_OUT1 : g_OUT0);

    int t0 = blockIdx.x * blockDim.x + threadIdx.x;
    int c4 = (t0 & 15) * 4;
    float4 sc = *reinterpret_cast<const float4*>(&g_SS[c4]);
    float4 sh = *reinterpret_cast<const float4*>(&g_SS[64 + c4]);
    float w = g_SS[128];
    int total = N * 16;
    int stride = gridDim.x * blockDim.x;   // 512*256, multiple of 16
    for (int i = t0; i < total; i += stride) {
        float4 v = AGG4[i];
        float4 o;
        o.x = fmaxf(fmaf(v.x, sc.x, sh.x), 0.f);
        o.y = fmaxf(fmaf(v.y, sc.y, sh.y), 0.f);
        o.z = fmaxf(fmaf(v.z, sc.z, sh.z), 0.f);
        o.w = fmaxf(fmaf(v.w, sc.w, sh.w), 0.f);
        if (layer > 0) {
            float4 p = PREV4[i];
            o.x = fmaf(0.7f, p.x, o.x);
            o.y = fmaf(0.7f, p.y, o.y);
            o.z = fmaf(0.7f, p.z, o.z);
            o.w = fmaf(0.7f, p.w, o.w);
        }
        OUT4[i] = o;
        if (layer == 0) {
            EMB4[i] = make_float4(w * o.x, w * o.y, w * o.z, w * o.w);
        } else {
            float4 e = EMB4[i];
            e.x = fmaf(w, o.x, e.x);
            e.y = fmaf(w, o.y, e.y);
            e.z = fmaf(w, o.z, e.z);
            e.w = fmaf(w, o.w, e.w);
            EMB4[i] = e;
        }
    }
}

// ---------------------------------------------------------------------------
// Host launcher — kernel launches only, no other CUDA API calls.
// ---------------------------------------------------------------------------

extern "C" void kernel_launch(void* const* d_in, const int* in_sizes, int n_in,
                              void* d_out, int out_size) {
    const float* feat  = (const float*)d_in[0];
    const int* ewords  = (const int*)d_in[1];   // int32 or int64 (probed on device)
    const float* W0    = (const float*)d_in[2];
    // d_in[3] = b0 (cancels through BN mean subtraction)
    const float* Wh    = (const float*)d_in[4];
    // d_in[5] = bh (same)
    const float* gamma = (const float*)d_in[6];
    const float* beta  = (const float*)d_in[7];
    const float* lw    = (const float*)d_in[8];
    float* out         = (float*)d_out;

    int hid    = in_sizes[3];                 // 64
    int in_dim = in_sizes[2] / hid;           // 2000
    int N      = in_sizes[0] / in_dim;        // 50000
    int E      = in_sizes[1] / 2;             // 1.6M logical edges
    int L      = in_sizes[8];                 // 4

    int nb = (N + SBS - 1) / SBS;             // 196 scan blocks

    // --- dtype probe + CSR build + normalization coefficients ---
    init_kernel<<<(N + 255) / 256, 256>>>(N);
    detect_kernel<<<(E / 2 + 255) / 256, 256>>>(ewords, E);
    count_kernel<<<(E + 255) / 256, 256>>>(ewords, E);
    dinv_kernel<<<(N + 255) / 256, 256>>>(N);
    scan1_kernel<<<nb, SBS>>>(N);
    scan2_kernel<<<1, SBS>>>(nb);
    scan3_kernel<<<(N + 255) / 256, 256>>>(N, E);
    fill_kernel<<<(E + 255) / 256, 256>>>(ewords, E);

    int gather_blocks = (N * 32 + 255) / 256;

    for (int layer = 0; layer < L; layer++) {
        int src_sel = (layer == 0) ? 0 : (((layer - 1) & 1) ? 2 : 1);
        const float* W = (layer == 0) ? W0 : (Wh + (size_t)(layer - 1) * hid * hid);
        int K = (layer == 0) ? in_dim : hid;

        gemm64_kernel<<<(N + 127) / 128, 256>>>(feat, src_sel, W, N, K);
        gather_kernel<<<gather_blocks, 256>>>(N);
        bn_stats_kernel<<<STATS_BLOCKS, 256>>>(N);
        bn_finalize_kernel<<<1, 256>>>(gamma, beta, lw, layer, L, N);
        bn_norm_kernel<<<512, 256>>>((float4*)out, N, layer);
    }
}

// round 4
// speedup vs baseline: 1.4665x; 1.4665x over previous
#include <cuda_runtime.h>
#include <cuda_bf16.h>
#include <cstdint>

// ---------------------------------------------------------------------------
// PopulationGNN: 4-layer GCN, N=50000, IN_DIM=2000, HID=64, E=1.6M
// CSR-by-destination build once per launch, then per layer:
// TF32 tensor-core GEMM -> warp-per-node register gather (self-loop fused) ->
// BN stats (2-stage deterministic) -> BN finalize -> norm/relu/res/emb fused.
// ---------------------------------------------------------------------------

#define HID 64
#define MAXN 50048
#define MAXE 1600256
#define STATS_BLOCKS 256
#define SBS 256
#define MAXSB 256

__device__ __align__(16) float g_XW[MAXN * HID];
__device__ __align__(16) float g_AGG[MAXN * HID];
__device__ __align__(16) float g_OUT0[MAXN * HID];
__device__ __align__(16) float g_OUT1[MAXN * HID];
__device__ int   g_DEGI[MAXN];
__device__ float g_DINV[MAXN];
__device__ int   g_ESRC[MAXE];
__device__ float g_EW[MAXE];
__device__ int   g_ROWPTR[MAXN + 1];
__device__ int   g_CUR[MAXN];
__device__ int   g_ROWEXC[MAXN];
__device__ int   g_BTOT[MAXSB];
__device__ int   g_BOFF[MAXSB];
__device__ int   g_IS32;
__device__ __align__(16) float g_PART[STATS_BLOCKS * 128];
__device__ __align__(16) float g_SS[132];

// ---------------------------------------------------------------------------
// Edge dtype probe + CSR build
// ---------------------------------------------------------------------------

__global__ void init_kernel(int n) {
    int i = blockIdx.x * blockDim.x + threadIdx.x;
    if (i < n) g_DEGI[i] = 0;
    if (i == 0) g_IS32 = 0;
}

__global__ void detect_kernel(const int* __restrict__ words, int E) {
    int i = blockIdx.x * blockDim.x + threadIdx.x;
    int idx = 2 * i + 1;
    if (idx < E && words[idx] != 0)
        atomicOr(&g_IS32, 1);
}

__device__ __forceinline__ void decode_edge(const int* __restrict__ words, int E, int e,
                                            int& s, int& d) {
    if (g_IS32) {
        s = words[e];
        d = words[E + e];
    } else {
        s = words[2 * e];
        d = words[2 * E + 2 * e];
    }
}

__global__ void count_kernel(const int* __restrict__ words, int E) {
    int e = blockIdx.x * blockDim.x + threadIdx.x;
    if (e < E) {
        int s, d;
        decode_edge(words, E, e, s, d);
        atomicAdd(&g_DEGI[d], 1);
    }
}

__global__ void dinv_kernel(int n) {
    int i = blockIdx.x * blockDim.x + threadIdx.x;
    if (i < n) g_DINV[i] = rsqrtf((float)g_DEGI[i] + 1.0f);
}

__global__ void scan1_kernel(int n) {
    __shared__ int sm[SBS];
    int t = threadIdx.x;
    int i = blockIdx.x * SBS + t;
    int v = (i < n) ? g_DEGI[i] : 0;
    sm[t] = v;
    __syncthreads();
#pragma unroll
    for (int off = 1; off < SBS; off <<= 1) {
        int y = (t >= off) ? sm[t - off] : 0;
        __syncthreads();
        sm[t] += y;
        __syncthreads();
    }
    if (i < n) g_ROWEXC[i] = sm[t] - v;
    if (t == SBS - 1) g_BTOT[blockIdx.x] = sm[t];
}

__global__ void scan2_kernel(int nb) {
    __shared__ int sm[SBS];
    int t = threadIdx.x;
    int v = (t < nb) ? g_BTOT[t] : 0;
    sm[t] = v;
    __syncthreads();
#pragma unroll
    for (int off = 1; off < SBS; off <<= 1) {
        int y = (t >= off) ? sm[t - off] : 0;
        __syncthreads();
        sm[t] += y;
        __syncthreads();
    }
    if (t < nb) g_BOFF[t] = sm[t] - v;
}

__global__ void scan3_kernel(int n, int E) {
    int i = blockIdx.x * blockDim.x + threadIdx.x;
    if (i < n) {
        int r = g_ROWEXC[i] + g_BOFF[i / SBS];
        g_ROWPTR[i] = r;
        g_CUR[i] = r;
    }
    if (i == 0) g_ROWPTR[n] = E;
}

__global__ void fill_kernel(const int* __restrict__ words, int E) {
    int e = blockIdx.x * blockDim.x + threadIdx.x;
    if (e < E) {
        int s, d;
        decode_edge(words, E, e, s, d);
        int pos = atomicAdd(&g_CUR[d], 1);
        g_ESRC[pos] = s;
        g_EW[pos] = g_DINV[s] * g_DINV[d];
    }
}

// ---------------------------------------------------------------------------
// TF32 tensor-core GEMM: A[M,K] @ W[K,64] -> g_XW[M,64]
// BM=128, BN=64, BK=32, 256 threads (8 warps), warp tile 32x32 via m16n8k8.
// Register-staged pipeline: LDG next tile while computing current smem tile.
// ---------------------------------------------------------------------------

__device__ __forceinline__ uint32_t to_tf32(float x) {
    uint32_t u;
    asm("cvt.rna.tf32.f32 %0, %1;" : "=r"(u) : "f"(__float_as_uint(x) ,x));
    return u;
}

// (fixed-form helper; see below for actual use)
__device__ __forceinline__ uint32_t f2tf32(float x) {
    uint32_t out;
    asm("cvt.rna.tf32.f32 %0, %1;" : "=r"(out) : "f"(x));
    return out;
}

__device__ __forceinline__ void mma_tf32(float& c0, float& c1, float& c2, float& c3,
                                         uint32_t a0, uint32_t a1, uint32_t a2, uint32_t a3,
                                         uint32_t b0, uint32_t b1) {
    asm volatile(
        "mma.sync.aligned.m16n8k8.row.col.f32.tf32.tf32.f32 "
        "{%0,%1,%2,%3}, {%4,%5,%6,%7}, {%8,%9}, {%0,%1,%2,%3};"
        : "+f"(c0), "+f"(c1), "+f"(c2), "+f"(c3)
        : "r"(a0), "r"(a1), "r"(a2), "r"(a3), "r"(b0), "r"(b1));
}

__global__ void __launch_bounds__(256, 2)
gemm_tf32_kernel(const float* __restrict__ feat, int src_sel,
                 const float* __restrict__ W, int M, int K) {
    __shared__ uint32_t As[128][36];   // [m][k] tf32, stride 36 (bank: 4m+k, conflict-free)
    __shared__ uint32_t Bs[32][72];    // [k][n] tf32, stride 72 (bank: 8k+n, conflict-free)

    const float* A = (src_sel == 0) ? feat : (src_sel == 1 ? g_OUT0 : g_OUT1);

    int t = threadIdx.x;
    int m0 = blockIdx.x * 128;
    int warp = t >> 5;
    int lane = t & 31;
    int wm = (warp >> 1) * 32;   // warp row base 0/32/64/96
    int wn = (warp & 1) * 32;    // warp col base 0/32
    int fr = lane >> 2;          // 0..7
    int fc = lane & 3;           // 0..3

    float acc[2][4][4];
#pragma unroll
    for (int i = 0; i < 2; i++)
#pragma unroll
        for (int j = 0; j < 4; j++)
#pragma unroll
            for (int q = 0; q < 4; q++) acc[i][j][q] = 0.0f;

    // Staging registers
    float4 aReg[4];
    float4 bReg[2];

    // A-tile mapping: idx = t + i*256 -> row = idx>>3 (0..127), kc = idx&7 (float4 chunk)
    // B-tile mapping: idx = t + i*256 -> krow = idx>>4 (0..31), nc = idx&15 (float4 chunk)

    auto load_tile = [&](int k0) {
#pragma unroll
        for (int i = 0; i < 4; i++) {
            int idx = t + i * 256;
            int row = idx >> 3;
            int kc = idx & 7;
            int gr = m0 + row;
            int gk = k0 + kc * 4;
            aReg[i] = make_float4(0.f, 0.f, 0.f, 0.f);
            if (gr < M && gk < K)
                aReg[i] = *reinterpret_cast<const float4*>(&A[(size_t)gr * K + gk]);
        }
#pragma unroll
        for (int i = 0; i < 2; i++) {
            int idx = t + i * 256;
            int krow = idx >> 4;
            int nc = idx & 15;
            int gk = k0 + krow;
            bReg[i] = make_float4(0.f, 0.f, 0.f, 0.f);
            if (gk < K)
                bReg[i] = *reinterpret_cast<const float4*>(&W[(size_t)gk * HID + nc * 4]);
        }
    };

    auto store_tile = [&]() {
#pragma unroll
        for (int i = 0; i < 4; i++) {
            int idx = t + i * 256;
            int row = idx >> 3;
            int kc = idx & 7;
            uint32_t* p = &As[row][kc * 4];
            p[0] = f2tf32(aReg[i].x);
            p[1] = f2tf32(aReg[i].y);
            p[2] = f2tf32(aReg[i].z);
            p[3] = f2tf32(aReg[i].w);
        }
#pragma unroll
        for (int i = 0; i < 2; i++) {
            int idx = t + i * 256;
            int krow = idx >> 4;
            int nc = idx & 15;
            uint32_t* p = &Bs[krow][nc * 4];
            p[0] = f2tf32(bReg[i].x);
            p[1] = f2tf32(bReg[i].y);
            p[2] = f2tf32(bReg[i].z);
            p[3] = f2tf32(bReg[i].w);
        }
    };

    load_tile(0);

    for (int k0 = 0; k0 < K; k0 += 32) {
        __syncthreads();
        store_tile();
        __syncthreads();
        if (k0 + 32 < K) load_tile(k0 + 32);

#pragma unroll
        for (int kk = 0; kk < 32; kk += 8) {
            uint32_t af[2][4];
#pragma unroll
            for (int i = 0; i < 2; i++) {
                int rb = wm + i * 16 + fr;
                af[i][0] = As[rb][kk + fc];
                af[i][1] = As[rb + 8][kk + fc];
                af[i][2] = As[rb][kk + fc + 4];
                af[i][3] = As[rb + 8][kk + fc + 4];
            }
            uint32_t bf[4][2];
#pragma unroll
            for (int j = 0; j < 4; j++) {
                int nb = wn + j * 8 + fr;
                bf[j][0] = Bs[kk + fc][nb];
                bf[j][1] = Bs[kk + fc + 4][nb];
            }
#pragma unroll
            for (int i = 0; i < 2; i++)
#pragma unroll
                for (int j = 0; j < 4; j++)
                    mma_tf32(acc[i][j][0], acc[i][j][1], acc[i][j][2], acc[i][j][3],
                             af[i][0], af[i][1], af[i][2], af[i][3],
                             bf[j][0], bf[j][1]);
        }
    }

    // Epilogue: c0/c1 -> (row, col..col+1), c2/c3 -> (row+8, col..col+1)
#pragma unroll
    for (int i = 0; i < 2; i++) {
#pragma unroll
        for (int j = 0; j < 4; j++) {
            int row = m0 + wm + i * 16 + fr;
            int col = wn + j * 8 + fc * 2;
            if (row < M)
                *reinterpret_cast<float2*>(&g_XW[(size_t)row * HID + col]) =
                    make_float2(acc[i][j][0], acc[i][j][1]);
            if (row + 8 < M)
                *reinterpret_cast<float2*>(&g_XW[(size_t)(row + 8) * HID + col]) =
                    make_float2(acc[i][j][2], acc[i][j][3]);
        }
    }
}

// ---------------------------------------------------------------------------
// Gather: warp per node. AGG[v] = snorm*XW[v] + sum_{e in CSR[v]} w_e*XW[src_e]
// ---------------------------------------------------------------------------

__global__ void gather_kernel(int N) {
    int gid = blockIdx.x * blockDim.x + threadIdx.x;
    int v = gid >> 5;
    int lane = gid & 31;
    if (v >= N) return;

    int beg = g_ROWPTR[v];
    int end = g_ROWPTR[v + 1];
    float dn = g_DINV[v];
    float sn = dn * dn;
    float a0 = g_XW[v * HID + lane] * sn;
    float a1 = g_XW[v * HID + 32 + lane] * sn;

    int j = beg;
    for (; j + 1 < end; j += 2) {
        int s0 = g_ESRC[j];
        int s1 = g_ESRC[j + 1];
        float w0 = g_EW[j];
        float w1 = g_EW[j + 1];
        float x00 = g_XW[s0 * HID + lane];
        float x01 = g_XW[s0 * HID + 32 + lane];
        float x10 = g_XW[s1 * HID + lane];
        float x11 = g_XW[s1 * HID + 32 + lane];
        a0 = fmaf(w0, x00, a0);
        a1 = fmaf(w0, x01, a1);
        a0 = fmaf(w1, x10, a0);
        a1 = fmaf(w1, x11, a1);
    }
    if (j < end) {
        int s0 = g_ESRC[j];
        float w0 = g_EW[j];
        a0 = fmaf(w0, g_XW[s0 * HID + lane], a0);
        a1 = fmaf(w0, g_XW[s0 * HID + 32 + lane], a1);
    }

    g_AGG[v * HID + lane] = a0;
    g_AGG[v * HID + 32 + lane] = a1;
}

// ---------------------------------------------------------------------------
// BN stats / finalize / norm
// ---------------------------------------------------------------------------

__global__ void bn_stats_kernel(int N) {
    __shared__ float4 ssum[256];
    __shared__ float4 ssq[256];
    const float4* AGG4 = reinterpret_cast<const float4*>(g_AGG);
    int t = threadIdx.x;
    int stride = gridDim.x * blockDim.x;
    int total = N * 16;
    float4 s = make_float4(0.f, 0.f, 0.f, 0.f);
    float4 q = make_float4(0.f, 0.f, 0.f, 0.f);
    for (int i = blockIdx.x * blockDim.x + t; i < total; i += stride) {
        float4 v = AGG4[i];
        s.x += v.x; s.y += v.y; s.z += v.z; s.w += v.w;
        q.x += v.x * v.x; q.y += v.y * v.y; q.z += v.z * v.z; q.w += v.w * v.w;
    }
    ssum[t] = s;
    ssq[t] = q;
    __syncthreads();
    for (int off = 128; off >= 16; off >>= 1) {
        if (t < off) {
            float4 a = ssum[t], b = ssum[t + off];
            ssum[t] = make_float4(a.x + b.x, a.y + b.y, a.z + b.z, a.w + b.w);
            float4 c = ssq[t], d = ssq[t + off];
            ssq[t] = make_float4(c.x + d.x, c.y + d.y, c.z + d.z, c.w + d.w);
        }
        __syncthreads();
    }
    if (t < 16) {
        *reinterpret_cast<float4*>(&g_PART[blockIdx.x * 128 + t * 4]) = ssum[t];
        *reinterpret_cast<float4*>(&g_PART[blockIdx.x * 128 + 64 + t * 4]) = ssq[t];
    }
}

__global__ void bn_finalize_kernel(const float* __restrict__ gamma,
                                   const float* __restrict__ beta,
                                   const float* __restrict__ lw,
                                   int layer, int L, int N) {
    __shared__ float s_s[256];
    __shared__ float s_q[256];
    int t = threadIdx.x;
    int c = t & 63;
    int g0 = t >> 6;
    float s = 0.f, q = 0.f;
    for (int g = g0; g < STATS_BLOCKS; g += 4) {
        s += g_PART[g * 128 + c];
        q += g_PART[g * 128 + 64 + c];
    }
    s_s[t] = s;
    s_q[t] = q;
    __syncthreads();
    if (t < 128) { s_s[t] += s_s[t + 128]; s_q[t] += s_q[t + 128]; }
    __syncthreads();
    if (t < 64) {
        float S = s_s[t] + s_s[t + 64];
        float Q = s_q[t] + s_q[t + 64];
        float invN = 1.0f / (float)N;
        float mean = S * invN;
        float var = Q * invN - mean * mean;
        float inv = rsqrtf(var + 1e-5f);
        float sc = gamma[layer * HID + c] * inv;
        g_SS[c] = sc;
        g_SS[64 + c] = beta[layer * HID + c] - mean * sc;
    }
    if (t == 0) {
        float se = 0.f;
        for (int j = 0; j < L; j++) se += expf(lw[j]);
        g_SS[128] = expf(lw[layer]) / se;
    }
}

__global__ void bn_norm_kernel(float4* __restrict__ EMB4, int N, int layer) {
    const float4* AGG4  = reinterpret_cast<const float4*>(g_AGG);
    const float4* PREV4 = reinterpret_cast<const float4*>((layer & 1) ? g_OUT0 : g_OUT1);
    float4* OUT4        = reinterpret_cast<float4*>((layer & 1) ? g_OUT1 : g_OUT0);

    int t0 = blockIdx.x * blockDim.x + threadIdx.x;
    int c4 = (t0 & 15) * 4;
    float4 sc = *reinterpret_cast<const float4*>(&g_SS[c4]);
    float4 sh = *reinterpret_cast<const float4*>(&g_SS[64 + c4]);
    float w = g_SS[128];
    int total = N * 16;
    int stride = gridDim.x * blockDim.x;
    for (int i = t0; i < total; i += stride) {
        float4 v = AGG4[i];
        float4 o;
        o.x = fmaxf(fmaf(v.x, sc.x, sh.x), 0.f);
        o.y = fmaxf(fmaf(v.y, sc.y, sh.y), 0.f);
        o.z = fmaxf(fmaf(v.z, sc.z, sh.z), 0.f);
        o.w = fmaxf(fmaf(v.w, sc.w, sh.w), 0.f);
        if (layer > 0) {
            float4 p = PREV4[i];
            o.x = fmaf(0.7f, p.x, o.x);
            o.y = fmaf(0.7f, p.y, o.y);
            o.z = fmaf(0.7f, p.z, o.z);
            o.w = fmaf(0.7f, p.w, o.w);
        }
        OUT4[i] = o;
        if (layer == 0) {
            EMB4[i] = make_float4(w * o.x, w * o.y, w * o.z, w * o.w);
        } else {
            float4 e = EMB4[i];
            e.x = fmaf(w, o.x, e.x);
            e.y = fmaf(w, o.y, e.y);
            e.z = fmaf(w, o.z, e.z);
            e.w = fmaf(w, o.w, e.w);
            EMB4[i] = e;
        }
    }
}

// ---------------------------------------------------------------------------
// Host launcher — kernel launches only.
// ---------------------------------------------------------------------------

extern "C" void kernel_launch(void* const* d_in, const int* in_sizes, int n_in,
                              void* d_out, int out_size) {
    const float* feat  = (const float*)d_in[0];
    const int* ewords  = (const int*)d_in[1];
    const float* W0    = (const float*)d_in[2];
    const float* Wh    = (const float*)d_in[4];
    const float* gamma = (const float*)d_in[6];
    const float* beta  = (const float*)d_in[7];
    const float* lw    = (const float*)d_in[8];
    float* out         = (float*)d_out;

    int hid    = in_sizes[3];
    int in_dim = in_sizes[2] / hid;
    int N      = in_sizes[0] / in_dim;
    int E      = in_sizes[1] / 2;
    int L      = in_sizes[8];

    int nb = (N + SBS - 1) / SBS;

    init_kernel<<<(N + 255) / 256, 256>>>(N);
    detect_kernel<<<(E / 2 + 255) / 256, 256>>>(ewords, E);
    count_kernel<<<(E + 255) / 256, 256>>>(ewords, E);
    dinv_kernel<<<(N + 255) / 256, 256>>>(N);
    scan1_kernel<<<nb, SBS>>>(N);
    scan2_kernel<<<1, SBS>>>(nb);
    scan3_kernel<<<(N + 255) / 256, 256>>>(N, E);
    fill_kernel<<<(E + 255) / 256, 256>>>(ewords, E);

    int gather_blocks = (N * 32 + 255) / 256;

    for (int layer = 0; layer < L; layer++) {
        int src_sel = (layer == 0) ? 0 : (((layer - 1) & 1) ? 2 : 1);
        const float* W = (layer == 0) ? W0 : (Wh + (size_t)(layer - 1) * hid * hid);
        int K = (layer == 0) ? in_dim : hid;

        gemm_tf32_kernel<<<(N + 127) / 128, 256>>>(feat, src_sel, W, N, K);
        gather_kernel<<<gather_blocks, 256>>>(N);
        bn_stats_kernel<<<STATS_BLOCKS, 256>>>(N);
        bn_finalize_kernel<<<1, 256>>>(gamma, beta, lw, layer, L, N);
        bn_norm_kernel<<<512, 256>>>((float4*)out, N, layer);
    }
}